// round 1
// baseline (speedup 1.0000x reference)
#include <cuda_runtime.h>

#define Nn   6144
#define FIN  256
#define FH   64
#define Hh   4
#define FO   32
#define JSPLIT 3

// ---------------- scratch (static device globals; no allocation) ----------------
__device__ float g_hcat[Nn * FIN];                 // layer-1 h, 4 heads concatenated [N][256]
__device__ float g_s1[Hh * Nn];
__device__ float g_s2[Hh * Nn];
__device__ float g_pnum[(size_t)JSPLIT * Nn * FIN]; // partial numerators per j-split
__device__ float g_pden[JSPLIT * Hh * Nn];          // partial denominators
__device__ float g_x2[Nn * FH];                     // layer-1 output (head-mean)
__device__ float g_h2[Nn * FO];
__device__ float g_s1b[Nn];
__device__ float g_s2b[Nn];

// ---------------- K1: hcat = x @ Wcat (per-head GEMM, BN=64 == one head) ----------------
__global__ __launch_bounds__(256) void k1_gemm(const float* __restrict__ x,
                                               const float* __restrict__ Wh) {
    __shared__ __align__(16) float As[16][68];
    __shared__ __align__(16) float Bs[16][68];
    const int i0   = blockIdx.x * 64;
    const int head = blockIdx.y;
    const int tid  = threadIdx.x;
    const int tx = tid & 15, ty = tid >> 4;
    const float* Wb = Wh + head * (FIN * FH);
    float acc[4][4] = {};
    for (int kk = 0; kk < FIN; kk += 16) {
        for (int t = tid; t < 1024; t += 256) {
            int m = t >> 4, kl = t & 15;
            As[kl][m] = x[(i0 + m) * FIN + kk + kl];
        }
        for (int t = tid; t < 1024; t += 256) {
            int kl = t >> 6, n = t & 63;
            Bs[kl][n] = Wb[(kk + kl) * FH + n];
        }
        __syncthreads();
#pragma unroll
        for (int k = 0; k < 16; ++k) {
            float4 a4 = *(const float4*)&As[k][ty * 4];
            float4 b4 = *(const float4*)&Bs[k][tx * 4];
            float av[4] = {a4.x, a4.y, a4.z, a4.w};
            float bv[4] = {b4.x, b4.y, b4.z, b4.w};
#pragma unroll
            for (int i = 0; i < 4; ++i)
#pragma unroll
                for (int j = 0; j < 4; ++j)
                    acc[i][j] = fmaf(av[i], bv[j], acc[i][j]);
        }
        __syncthreads();
    }
#pragma unroll
    for (int i = 0; i < 4; ++i) {
        float4 v = make_float4(acc[i][0], acc[i][1], acc[i][2], acc[i][3]);
        *(float4*)&g_hcat[(i0 + ty * 4 + i) * FIN + head * FH + tx * 4] = v;
    }
}

// ---------------- K2: s1/s2 per head (64-dim dots) ----------------
__global__ __launch_bounds__(256) void k2_scores(const float* __restrict__ a_heads) {
    __shared__ float as[128];
    const int hd = blockIdx.y;
    const int i  = blockIdx.x * 256 + threadIdx.x;
    if (threadIdx.x < 128) as[threadIdx.x] = a_heads[hd * 128 + threadIdx.x];
    __syncthreads();
    const float4* hp = (const float4*)g_hcat + (size_t)i * (FIN / 4) + hd * (FH / 4);
    float s1 = 0.f, s2 = 0.f;
#pragma unroll
    for (int k = 0; k < 16; ++k) {
        float4 v = hp[k];
        s1 = fmaf(v.x, as[k * 4 + 0], s1);
        s1 = fmaf(v.y, as[k * 4 + 1], s1);
        s1 = fmaf(v.z, as[k * 4 + 2], s1);
        s1 = fmaf(v.w, as[k * 4 + 3], s1);
        s2 = fmaf(v.x, as[64 + k * 4 + 0], s2);
        s2 = fmaf(v.y, as[64 + k * 4 + 1], s2);
        s2 = fmaf(v.z, as[64 + k * 4 + 2], s2);
        s2 = fmaf(v.w, as[64 + k * 4 + 3], s2);
    }
    g_s1[hd * Nn + i] = s1;
    g_s2[hd * Nn + i] = s2;
}

// ---------------- K3: fused layer-1 attention (flash-style, j-split partials) ----------------
// block = 64 rows x 4 heads (thread owns a full 64-feature head row), grid (96, JSPLIT)
__global__ __launch_bounds__(256, 2) void k3_attn1(const int* __restrict__ adj) {
    __shared__ int    adjs[64 * 33];
    __shared__ float4 hs4[32 * 64];        // 32 j-rows x 256 feats
    __shared__ float  s2s[128];            // 4 heads x 32
    const int tid = threadIdx.x;
    const int r  = tid & 63;
    const int hd = tid >> 6;
    const int i0 = blockIdx.x * 64;
    const int js = blockIdx.y;
    const int jbase = js * (Nn / JSPLIT);
    const float s1r = g_s1[hd * Nn + i0 + r];
    float4 acc[16];
#pragma unroll
    for (int k = 0; k < 16; ++k) acc[k] = make_float4(0.f, 0.f, 0.f, 0.f);
    float den = 0.f;
    const float4* hc4 = (const float4*)g_hcat;

    for (int jt = 0; jt < (Nn / JSPLIT) / 32; ++jt) {
        const int j0 = jbase + jt * 32;
        for (int t = tid; t < 2048; t += 256) {
            int rr = t >> 5, cc = t & 31;
            adjs[rr * 33 + cc] = adj[(i0 + rr) * Nn + j0 + cc];
        }
        for (int t = tid; t < 2048; t += 256) {
            int rr = t >> 6, c4 = t & 63;
            hs4[rr * 64 + c4] = hc4[(size_t)(j0 + rr) * 64 + c4];
        }
        if (tid < 128) s2s[tid] = g_s2[(tid >> 5) * Nn + j0 + (tid & 31)];
        __syncthreads();
        for (int jj = 0; jj < 32; ++jj) {
            float e = s1r + s2s[hd * 32 + jj];
            e = (e > 0.f) ? e : 0.2f * e;
            float w = (adjs[r * 33 + jj] > 0) ? __expf(e) : 0.f;
            den += w;
            const float4* hv = hs4 + jj * 64 + hd * 16;
#pragma unroll
            for (int k = 0; k < 16; ++k) {
                float4 h4 = hv[k];
                acc[k].x = fmaf(w, h4.x, acc[k].x);
                acc[k].y = fmaf(w, h4.y, acc[k].y);
                acc[k].z = fmaf(w, h4.z, acc[k].z);
                acc[k].w = fmaf(w, h4.w, acc[k].w);
            }
        }
        __syncthreads();
    }
    float4* pn = (float4*)(g_pnum + (size_t)js * Nn * FIN + (size_t)(i0 + r) * FIN + hd * FH);
#pragma unroll
    for (int k = 0; k < 16; ++k) pn[k] = acc[k];
    g_pden[(js * Hh + hd) * Nn + i0 + r] = den;
}

// ---------------- K3b: combine j-splits, normalize, elu, head-mean ----------------
__global__ __launch_bounds__(256) void k3b_combine() {
    const int idx = blockIdx.x * 256 + threadIdx.x;   // < Nn*FH
    const int i = idx >> 6, f = idx & 63;
    float x2v = 0.f;
#pragma unroll
    for (int hd = 0; hd < Hh; ++hd) {
        float num = 0.f, den = 0.f;
#pragma unroll
        for (int js = 0; js < JSPLIT; ++js) {
            num += g_pnum[(size_t)js * Nn * FIN + (size_t)i * FIN + hd * FH + f];
            den += g_pden[(js * Hh + hd) * Nn + i];
        }
        float o = num / den;
        o = (o > 0.f) ? o : (__expf(o) - 1.f);
        x2v += o;
    }
    g_x2[idx] = x2v * 0.25f;
}

// ---------------- K4: h2 = x2 @ W_out ----------------
__global__ __launch_bounds__(256) void k4_gemm2(const float* __restrict__ Wo) {
    __shared__ float Ws[64 * 32];
    __shared__ float xs[8][64];
    const int tid = threadIdx.x;
    const int i0 = blockIdx.x * 8;
    const int li = tid >> 5, f = tid & 31;
    for (int t = tid; t < 2048; t += 256) Ws[t] = Wo[t];
    for (int t = tid; t < 512; t += 256) xs[t >> 6][t & 63] = g_x2[(i0 + (t >> 6)) * 64 + (t & 63)];
    __syncthreads();
    float acc = 0.f;
#pragma unroll
    for (int k = 0; k < 64; ++k) acc = fmaf(xs[li][k], Ws[k * 32 + f], acc);
    g_h2[(i0 + li) * 32 + f] = acc;
}

// ---------------- K5: s1b/s2b for output layer ----------------
__global__ __launch_bounds__(256) void k5_scores2(const float* __restrict__ ao) {
    __shared__ float as[64];
    const int i = blockIdx.x * 256 + threadIdx.x;
    if (threadIdx.x < 64) as[threadIdx.x] = ao[threadIdx.x];
    __syncthreads();
    const float* hr = g_h2 + (size_t)i * 32;
    float s1 = 0.f, s2 = 0.f;
#pragma unroll
    for (int k = 0; k < 32; ++k) {
        float v = hr[k];
        s1 = fmaf(v, as[k], s1);
        s2 = fmaf(v, as[32 + k], s2);
    }
    g_s1b[i] = s1;
    g_s2b[i] = s2;
}

// ---------------- K6: fused layer-2 attention + final elu ----------------
// block = 32 rows x 4 feature-groups (8 feats each), grid 192
__device__ __forceinline__ float elu1(float v) { return v > 0.f ? v : (__expf(v) - 1.f); }

__global__ __launch_bounds__(128) void k6_attn2(const int* __restrict__ adj,
                                                float* __restrict__ out) {
    __shared__ int    adjs[32 * 65];
    __shared__ float4 h2s4[64 * 8];
    __shared__ float  s2s[64];
    const int tid = threadIdx.x;
    const int r = tid & 31;
    const int c = tid >> 5;            // 0..3, feats c*8..c*8+7
    const int i0 = blockIdx.x * 32;
    const float s1r = g_s1b[i0 + r];
    float4 a0 = make_float4(0.f, 0.f, 0.f, 0.f), a1 = a0;
    float den = 0.f;
    const float4* h2v = (const float4*)g_h2;

    for (int jt = 0; jt < Nn / 64; ++jt) {
        const int j0 = jt * 64;
        for (int t = tid; t < 2048; t += 128) {
            int rr = t >> 6, cc = t & 63;
            adjs[rr * 65 + cc] = adj[(i0 + rr) * Nn + j0 + cc];
        }
        for (int t = tid; t < 512; t += 128) h2s4[t] = h2v[j0 * 8 + t];
        if (tid < 64) s2s[tid] = g_s2b[j0 + tid];
        __syncthreads();
        for (int jj = 0; jj < 64; ++jj) {
            float e = s1r + s2s[jj];
            e = (e > 0.f) ? e : 0.2f * e;
            float w = (adjs[r * 65 + jj] > 0) ? __expf(e) : 0.f;
            den += w;
            const float4* hv = h2s4 + jj * 8 + c * 2;
            float4 h0 = hv[0], h1 = hv[1];
            a0.x = fmaf(w, h0.x, a0.x); a0.y = fmaf(w, h0.y, a0.y);
            a0.z = fmaf(w, h0.z, a0.z); a0.w = fmaf(w, h0.w, a0.w);
            a1.x = fmaf(w, h1.x, a1.x); a1.y = fmaf(w, h1.y, a1.y);
            a1.z = fmaf(w, h1.z, a1.z); a1.w = fmaf(w, h1.w, a1.w);
        }
        __syncthreads();
    }
    const float inv = 1.f / den;
    float4 o0, o1;
    o0.x = elu1(a0.x * inv); o0.y = elu1(a0.y * inv);
    o0.z = elu1(a0.z * inv); o0.w = elu1(a0.w * inv);
    o1.x = elu1(a1.x * inv); o1.y = elu1(a1.y * inv);
    o1.z = elu1(a1.z * inv); o1.w = elu1(a1.w * inv);
    float4* op = (float4*)out + (size_t)(i0 + r) * 8 + c * 2;
    op[0] = o0;
    op[1] = o1;
}

// ---------------- launch ----------------
extern "C" void kernel_launch(void* const* d_in, const int* in_sizes, int n_in,
                              void* d_out, int out_size) {
    (void)in_sizes; (void)n_in; (void)out_size;
    const float* x  = (const float*)d_in[0];
    const int*   adj = (const int*)d_in[1];
    const float* Wh = (const float*)d_in[2];
    const float* ah = (const float*)d_in[3];
    const float* Wo = (const float*)d_in[4];
    const float* ao = (const float*)d_in[5];
    float* out = (float*)d_out;

    k1_gemm   <<<dim3(Nn / 64, Hh), 256>>>(x, Wh);
    k2_scores <<<dim3(Nn / 256, Hh), 256>>>(ah);
    k3_attn1  <<<dim3(Nn / 64, JSPLIT), 256>>>(adj);
    k3b_combine<<<(Nn * FH) / 256, 256>>>();
    k4_gemm2  <<<Nn / 8, 256>>>(Wo);
    k5_scores2<<<Nn / 256, 256>>>(ao);
    k6_attn2  <<<Nn / 32, 128>>>(adj, out);
}

// round 2
// speedup vs baseline: 1.6065x; 1.6065x over previous
#include <cuda_runtime.h>

#define Nn   6144
#define FIN  256
#define FH   64
#define Hh   4
#define FO   32
#define JSPLIT 3
#define BJ   16

// ---------------- scratch ----------------
__device__ float g_hcat[Nn * FIN];
__device__ float g_s1[Hh * Nn];
__device__ float g_s2[Hh * Nn];
__device__ float g_pnum[(size_t)JSPLIT * Nn * FIN];
__device__ float g_pden[JSPLIT * Hh * Nn];
__device__ float g_x2[Nn * FH];
__device__ float g_h2[Nn * FO];
__device__ float g_s1b[Nn];
__device__ float g_s2b[Nn];

// ---------------- K1: hcat = x @ W per head ----------------
__global__ __launch_bounds__(256) void k1_gemm(const float* __restrict__ x,
                                               const float* __restrict__ Wh) {
    __shared__ __align__(16) float As[16][68];
    __shared__ __align__(16) float Bs[16][68];
    const int i0   = blockIdx.x * 64;
    const int head = blockIdx.y;
    const int tid  = threadIdx.x;
    const int tx = tid & 15, ty = tid >> 4;
    const float* Wb = Wh + head * (FIN * FH);
    float acc[4][4] = {};
    for (int kk = 0; kk < FIN; kk += 16) {
        for (int t = tid; t < 1024; t += 256) {
            int m = t >> 4, kl = t & 15;
            As[kl][m] = x[(i0 + m) * FIN + kk + kl];
        }
        for (int t = tid; t < 1024; t += 256) {
            int kl = t >> 6, n = t & 63;
            Bs[kl][n] = Wb[(kk + kl) * FH + n];
        }
        __syncthreads();
#pragma unroll
        for (int k = 0; k < 16; ++k) {
            float4 a4 = *(const float4*)&As[k][ty * 4];
            float4 b4 = *(const float4*)&Bs[k][tx * 4];
            float av[4] = {a4.x, a4.y, a4.z, a4.w};
            float bv[4] = {b4.x, b4.y, b4.z, b4.w};
#pragma unroll
            for (int i = 0; i < 4; ++i)
#pragma unroll
                for (int j = 0; j < 4; ++j)
                    acc[i][j] = fmaf(av[i], bv[j], acc[i][j]);
        }
        __syncthreads();
    }
#pragma unroll
    for (int i = 0; i < 4; ++i) {
        float4 v = make_float4(acc[i][0], acc[i][1], acc[i][2], acc[i][3]);
        *(float4*)&g_hcat[(i0 + ty * 4 + i) * FIN + head * FH + tx * 4] = v;
    }
}

// ---------------- K2: s1/s2 per head ----------------
__global__ __launch_bounds__(256) void k2_scores(const float* __restrict__ a_heads) {
    __shared__ float as[128];
    const int hd = blockIdx.y;
    const int i  = blockIdx.x * 256 + threadIdx.x;
    if (threadIdx.x < 128) as[threadIdx.x] = a_heads[hd * 128 + threadIdx.x];
    __syncthreads();
    const float4* hp = (const float4*)g_hcat + (size_t)i * (FIN / 4) + hd * (FH / 4);
    float s1 = 0.f, s2 = 0.f;
#pragma unroll
    for (int k = 0; k < 16; ++k) {
        float4 v = hp[k];
        s1 = fmaf(v.x, as[k * 4 + 0], s1);
        s1 = fmaf(v.y, as[k * 4 + 1], s1);
        s1 = fmaf(v.z, as[k * 4 + 2], s1);
        s1 = fmaf(v.w, as[k * 4 + 3], s1);
        s2 = fmaf(v.x, as[64 + k * 4 + 0], s2);
        s2 = fmaf(v.y, as[64 + k * 4 + 1], s2);
        s2 = fmaf(v.z, as[64 + k * 4 + 2], s2);
        s2 = fmaf(v.w, as[64 + k * 4 + 3], s2);
    }
    g_s1[hd * Nn + i] = s1;
    g_s2[hd * Nn + i] = s2;
}

// ---------------- K3: fused layer-1 attention, register-blocked GEMM ----------------
// block: 256 threads. P-phase: thread (r=tid&63, jg=tid>>6) covers 4 j-cols x 4 heads.
// GEMM: thread (ty=tid>>5 rows ty*8..+8, tx=tid&31 feats tx*8..+8), 8x8 register tile.
__global__ __launch_bounds__(256, 2) void k3_attn1(const int* __restrict__ adj) {
    __shared__ float Pt[Hh][BJ][68];     // [head][k][row]
    __shared__ float Hs[BJ][260];        // [k][feat]
    __shared__ float s2s[64];            // [head][16]
    __shared__ float denp[4][Hh][64];    // [jg][head][row]
    const int tid = threadIdx.x;
    const int r = tid & 63, jg = tid >> 6;
    const int tx = tid & 31, ty = tid >> 5;
    const int hdx = tx >> 3;
    const int i0 = blockIdx.x * 64;
    const int js = blockIdx.y;
    const int jbase = js * (Nn / JSPLIT);
    float s1v[4];
#pragma unroll
    for (int hd = 0; hd < 4; ++hd) s1v[hd] = g_s1[hd * Nn + i0 + r];
    float den[4] = {0.f, 0.f, 0.f, 0.f};
    float acc[8][8] = {};
    // prefetch tile 0
    int4 av = *(const int4*)&adj[(size_t)(i0 + r) * Nn + jbase + jg * 4];
    float s2n = (tid < 64) ? g_s2[(tid >> 4) * Nn + jbase + (tid & 15)] : 0.f;
    const float4* hc4 = (const float4*)g_hcat;
    const int NT = (Nn / JSPLIT) / BJ;   // 128

    for (int t = 0; t < NT; ++t) {
        const int j0 = jbase + t * BJ;
        if (tid < 64) s2s[tid] = s2n;
#pragma unroll
        for (int p = 0; p < 4; ++p) {
            int idx = tid + p * 256;
            int row = idx >> 6, c4 = idx & 63;
            *(float4*)&Hs[row][c4 * 4] = hc4[(size_t)(j0 + row) * 64 + c4];
        }
        __syncthreads();
        // prefetch next tile while P/GEMM run
        int4 avn = av; float s2nn = s2n;
        if (t + 1 < NT) {
            avn = *(const int4*)&adj[(size_t)(i0 + r) * Nn + j0 + BJ + jg * 4];
            if (tid < 64) s2nn = g_s2[(tid >> 4) * Nn + j0 + BJ + (tid & 15)];
        }
        // P phase
        int a4[4] = {av.x, av.y, av.z, av.w};
#pragma unroll
        for (int hd = 0; hd < 4; ++hd) {
            const float s1r = s1v[hd];
#pragma unroll
            for (int jj = 0; jj < 4; ++jj) {
                float e = s1r + s2s[hd * 16 + jg * 4 + jj];
                e = (e > 0.f) ? e : 0.2f * e;
                float w = (a4[jj] > 0) ? __expf(e) : 0.f;
                den[hd] += w;
                Pt[hd][jg * 4 + jj][r] = w;
            }
        }
        __syncthreads();
        // GEMM: C[64x256] += P[64x16] * H[16x256]
#pragma unroll 4
        for (int k = 0; k < BJ; ++k) {
            float4 pA = *(const float4*)&Pt[hdx][k][ty * 8];
            float4 pB = *(const float4*)&Pt[hdx][k][ty * 8 + 4];
            float4 hA = *(const float4*)&Hs[k][tx * 8];
            float4 hB = *(const float4*)&Hs[k][tx * 8 + 4];
            float pv[8] = {pA.x, pA.y, pA.z, pA.w, pB.x, pB.y, pB.z, pB.w};
            float hv[8] = {hA.x, hA.y, hA.z, hA.w, hB.x, hB.y, hB.z, hB.w};
#pragma unroll
            for (int i = 0; i < 8; ++i)
#pragma unroll
                for (int j = 0; j < 8; ++j)
                    acc[i][j] = fmaf(pv[i], hv[j], acc[i][j]);
        }
        __syncthreads();
        av = avn; s2n = s2nn;
    }
    float* pn = g_pnum + (size_t)js * Nn * FIN;
#pragma unroll
    for (int i = 0; i < 8; ++i) {
        *(float4*)&pn[(size_t)(i0 + ty * 8 + i) * FIN + tx * 8] =
            make_float4(acc[i][0], acc[i][1], acc[i][2], acc[i][3]);
        *(float4*)&pn[(size_t)(i0 + ty * 8 + i) * FIN + tx * 8 + 4] =
            make_float4(acc[i][4], acc[i][5], acc[i][6], acc[i][7]);
    }
#pragma unroll
    for (int hd = 0; hd < 4; ++hd) denp[jg][hd][r] = den[hd];
    __syncthreads();
    {
        int hd = tid >> 6, rr = tid & 63;
        float d = denp[0][hd][rr] + denp[1][hd][rr] + denp[2][hd][rr] + denp[3][hd][rr];
        g_pden[(js * Hh + hd) * Nn + i0 + rr] = d;
    }
}

// ---------------- K3b: combine j-splits, normalize, elu, head-mean ----------------
__global__ __launch_bounds__(256) void k3b_combine() {
    const int idx = blockIdx.x * 256 + threadIdx.x;
    const int i = idx >> 6, f = idx & 63;
    float x2v = 0.f;
#pragma unroll
    for (int hd = 0; hd < Hh; ++hd) {
        float num = 0.f, den = 0.f;
#pragma unroll
        for (int js = 0; js < JSPLIT; ++js) {
            num += g_pnum[(size_t)js * Nn * FIN + (size_t)i * FIN + hd * FH + f];
            den += g_pden[(js * Hh + hd) * Nn + i];
        }
        float o = num / den;
        o = (o > 0.f) ? o : (__expf(o) - 1.f);
        x2v += o;
    }
    g_x2[idx] = x2v * 0.25f;
}

// ---------------- K4: h2 = x2 @ W_out ----------------
__global__ __launch_bounds__(256) void k4_gemm2(const float* __restrict__ Wo) {
    __shared__ float Ws[64 * 32];
    __shared__ float xs[8][64];
    const int tid = threadIdx.x;
    const int i0 = blockIdx.x * 8;
    const int li = tid >> 5, f = tid & 31;
    for (int t = tid; t < 2048; t += 256) Ws[t] = Wo[t];
    for (int t = tid; t < 512; t += 256) xs[t >> 6][t & 63] = g_x2[(i0 + (t >> 6)) * 64 + (t & 63)];
    __syncthreads();
    float acc = 0.f;
#pragma unroll
    for (int k = 0; k < 64; ++k) acc = fmaf(xs[li][k], Ws[k * 32 + f], acc);
    g_h2[(i0 + li) * 32 + f] = acc;
}

// ---------------- K5: s1b/s2b ----------------
__global__ __launch_bounds__(256) void k5_scores2(const float* __restrict__ ao) {
    __shared__ float as[64];
    const int i = blockIdx.x * 256 + threadIdx.x;
    if (threadIdx.x < 64) as[threadIdx.x] = ao[threadIdx.x];
    __syncthreads();
    const float* hr = g_h2 + (size_t)i * 32;
    float s1 = 0.f, s2 = 0.f;
#pragma unroll
    for (int k = 0; k < 32; ++k) {
        float v = hr[k];
        s1 = fmaf(v, as[k], s1);
        s2 = fmaf(v, as[32 + k], s2);
    }
    g_s1b[i] = s1;
    g_s2b[i] = s2;
}

// ---------------- K6: layer-2 attention, register-blocked ----------------
// 128 threads, 32-row tiles. P-phase: (r=tid&31, jg=tid>>5) covers 8 j-cols.
// GEMM: (ty=tid>>5 rows ty*8..+8, tx=tid&31 feat), 8x1 register tile.
__global__ __launch_bounds__(128) void k6_attn2(const int* __restrict__ adj,
                                                float* __restrict__ out) {
    __shared__ float Pt2[32][36];
    __shared__ float Hs2[32][36];
    __shared__ float s2s[32];
    __shared__ float denp[4][32];
    __shared__ float dinv[32];
    const int tid = threadIdx.x;
    const int r = tid & 31, jg = tid >> 5;
    const int tx = tid & 31, ty = tid >> 5;
    const int i0 = blockIdx.x * 32;
    const float s1r = g_s1b[i0 + r];
    float den = 0.f;
    float acc[8] = {};
    int4 av0 = *(const int4*)&adj[(size_t)(i0 + r) * Nn + jg * 8];
    int4 av1 = *(const int4*)&adj[(size_t)(i0 + r) * Nn + jg * 8 + 4];
    float s2n = (tid < 32) ? g_s2b[tid] : 0.f;
    const float4* h24 = (const float4*)g_h2;

    for (int t = 0; t < Nn / 32; ++t) {
        const int j0 = t * 32;
        if (tid < 32) s2s[tid] = s2n;
#pragma unroll
        for (int p = 0; p < 2; ++p) {
            int idx = tid + p * 128;
            int row = idx >> 3, c4 = idx & 7;
            *(float4*)&Hs2[row][c4 * 4] = h24[(size_t)(j0 + row) * 8 + c4];
        }
        __syncthreads();
        int4 b0 = av0, b1 = av1; float s2nn = s2n;
        if (t + 1 < Nn / 32) {
            b0 = *(const int4*)&adj[(size_t)(i0 + r) * Nn + j0 + 32 + jg * 8];
            b1 = *(const int4*)&adj[(size_t)(i0 + r) * Nn + j0 + 32 + jg * 8 + 4];
            if (tid < 32) s2nn = g_s2b[j0 + 32 + tid];
        }
        int a8[8] = {av0.x, av0.y, av0.z, av0.w, av1.x, av1.y, av1.z, av1.w};
#pragma unroll
        for (int jj = 0; jj < 8; ++jj) {
            float e = s1r + s2s[jg * 8 + jj];
            e = (e > 0.f) ? e : 0.2f * e;
            float w = (a8[jj] > 0) ? __expf(e) : 0.f;
            den += w;
            Pt2[jg * 8 + jj][r] = w;
        }
        __syncthreads();
#pragma unroll 8
        for (int k = 0; k < 32; ++k) {
            float4 pA = *(const float4*)&Pt2[k][ty * 8];
            float4 pB = *(const float4*)&Pt2[k][ty * 8 + 4];
            float hv = Hs2[k][tx];
            acc[0] = fmaf(pA.x, hv, acc[0]);
            acc[1] = fmaf(pA.y, hv, acc[1]);
            acc[2] = fmaf(pA.z, hv, acc[2]);
            acc[3] = fmaf(pA.w, hv, acc[3]);
            acc[4] = fmaf(pB.x, hv, acc[4]);
            acc[5] = fmaf(pB.y, hv, acc[5]);
            acc[6] = fmaf(pB.z, hv, acc[6]);
            acc[7] = fmaf(pB.w, hv, acc[7]);
        }
        __syncthreads();
        av0 = b0; av1 = b1; s2n = s2nn;
    }
    denp[jg][r] = den;
    __syncthreads();
    if (tid < 32) {
        float d = denp[0][tid] + denp[1][tid] + denp[2][tid] + denp[3][tid];
        dinv[tid] = 1.f / d;
    }
    __syncthreads();
#pragma unroll
    for (int i = 0; i < 8; ++i) {
        float v = acc[i] * dinv[ty * 8 + i];
        v = (v > 0.f) ? v : (__expf(v) - 1.f);
        out[(size_t)(i0 + ty * 8 + i) * FO + tx] = v;
    }
}

// ---------------- launch ----------------
extern "C" void kernel_launch(void* const* d_in, const int* in_sizes, int n_in,
                              void* d_out, int out_size) {
    (void)in_sizes; (void)n_in; (void)out_size;
    const float* x   = (const float*)d_in[0];
    const int*   adj = (const int*)d_in[1];
    const float* Wh  = (const float*)d_in[2];
    const float* ah  = (const float*)d_in[3];
    const float* Wo  = (const float*)d_in[4];
    const float* ao  = (const float*)d_in[5];
    float* out = (float*)d_out;

    k1_gemm    <<<dim3(Nn / 64, Hh), 256>>>(x, Wh);
    k2_scores  <<<dim3(Nn / 256, Hh), 256>>>(ah);
    k3_attn1   <<<dim3(Nn / 64, JSPLIT), 256>>>(adj);
    k3b_combine<<<(Nn * FH) / 256, 256>>>();
    k4_gemm2   <<<Nn / 8, 256>>>(Wo);
    k5_scores2 <<<Nn / 256, 256>>>(ao);
    k6_attn2   <<<Nn / 32, 128>>>(adj, out);
}

// round 4
// speedup vs baseline: 3.8026x; 2.3670x over previous
#include <cuda_runtime.h>
#include <cstdint>

#define Nn   6144
#define FIN  256
#define FH   64
#define Hh   4
#define FO   32
#define JSPLIT 3
#define KS3  (Nn / JSPLIT)       // 2048
#define NW   (Nn / 32)           // 192 bitmask words per row
#define LOG2E 1.4426950408889634f

// ---------------- scratch ----------------
__device__ float    g_hcat[Nn * FIN];
__device__ float    g_hT[FIN * Nn];
__device__ float    g_s1[Hh * Nn];
__device__ float    g_s2[Hh * Nn];
__device__ uint32_t g_adjbits[Nn * NW];
__device__ float    g_pnum[(size_t)JSPLIT * Nn * FIN];
__device__ float    g_pden[JSPLIT * Hh * Nn];
__device__ float    g_x2[Nn * FH];
__device__ float    g_h2[Nn * FO];
__device__ float    g_s1b[Nn];
__device__ float    g_s2b[Nn];
__device__ float    g_p2num[JSPLIT * Nn * FO];
__device__ float    g_p2den[JSPLIT * Nn];

// ---------------- helpers ----------------
__device__ __forceinline__ float ex2f(float x) {
    float y; asm("ex2.approx.f32 %0, %1;" : "=f"(y) : "f"(x)); return y;
}
__device__ __forceinline__ uint32_t f2tf32(float x) {
    uint32_t r; asm("cvt.rna.tf32.f32 %0, %1;" : "=r"(r) : "f"(x)); return r;
}
__device__ __forceinline__ void mma_tf32(float* c, const uint32_t* a, const uint32_t* b) {
    asm volatile(
        "mma.sync.aligned.m16n8k8.row.col.f32.tf32.tf32.f32 "
        "{%0,%1,%2,%3}, {%4,%5,%6,%7}, {%8,%9}, {%0,%1,%2,%3};\n"
        : "+f"(c[0]), "+f"(c[1]), "+f"(c[2]), "+f"(c[3])
        : "r"(a[0]), "r"(a[1]), "r"(a[2]), "r"(a[3]), "r"(b[0]), "r"(b[1]));
}

// ---------------- Kprep: pack adjacency to bitmasks ----------------
__global__ __launch_bounds__(256) void kprep(const int* __restrict__ adj) {
    const int gw = (blockIdx.x * 256 + threadIdx.x) >> 5;
    const int lane = threadIdx.x & 31;
    int v = adj[(size_t)gw * 32 + lane];
    unsigned m = __ballot_sync(0xffffffffu, v > 0);
    if (lane == 0) g_adjbits[gw] = m;
}

// ---------------- K1: hcat = x @ W per head ----------------
__global__ __launch_bounds__(256) void k1_gemm(const float* __restrict__ x,
                                               const float* __restrict__ Wh) {
    __shared__ __align__(16) float As[16][68];
    __shared__ __align__(16) float Bs[16][68];
    const int i0   = blockIdx.x * 64;
    const int head = blockIdx.y;
    const int tid  = threadIdx.x;
    const int tx = tid & 15, ty = tid >> 4;
    const float* Wb = Wh + head * (FIN * FH);
    float acc[4][4] = {};
    for (int kk = 0; kk < FIN; kk += 16) {
        for (int t = tid; t < 1024; t += 256) {
            int m = t >> 4, kl = t & 15;
            As[kl][m] = x[(i0 + m) * FIN + kk + kl];
        }
        for (int t = tid; t < 1024; t += 256) {
            int kl = t >> 6, n = t & 63;
            Bs[kl][n] = Wb[(kk + kl) * FH + n];
        }
        __syncthreads();
#pragma unroll
        for (int k = 0; k < 16; ++k) {
            float4 a4 = *(const float4*)&As[k][ty * 4];
            float4 b4 = *(const float4*)&Bs[k][tx * 4];
            float av[4] = {a4.x, a4.y, a4.z, a4.w};
            float bv[4] = {b4.x, b4.y, b4.z, b4.w};
#pragma unroll
            for (int i = 0; i < 4; ++i)
#pragma unroll
                for (int j = 0; j < 4; ++j)
                    acc[i][j] = fmaf(av[i], bv[j], acc[i][j]);
        }
        __syncthreads();
    }
#pragma unroll
    for (int i = 0; i < 4; ++i) {
        float4 v = make_float4(acc[i][0], acc[i][1], acc[i][2], acc[i][3]);
        *(float4*)&g_hcat[(i0 + ty * 4 + i) * FIN + head * FH + tx * 4] = v;
    }
}

// ---------------- K1t: g_hT = g_hcat^T ----------------
__global__ __launch_bounds__(256) void k1t_transpose() {
    __shared__ float t[32][33];
    const int tx = threadIdx.x & 31, ty = threadIdx.x >> 5;
    const int i0 = blockIdx.x * 32, f0 = blockIdx.y * 32;
#pragma unroll
    for (int k = 0; k < 4; ++k)
        t[ty + k * 8][tx] = g_hcat[(size_t)(i0 + ty + k * 8) * FIN + f0 + tx];
    __syncthreads();
#pragma unroll
    for (int k = 0; k < 4; ++k)
        g_hT[(size_t)(f0 + ty + k * 8) * Nn + i0 + tx] = t[tx][ty + k * 8];
}

// ---------------- K2: s1/s2 per head (pre-scaled by log2e) ----------------
__global__ __launch_bounds__(256) void k2_scores(const float* __restrict__ a_heads) {
    __shared__ float as[128];
    const int hd = blockIdx.y;
    const int i  = blockIdx.x * 256 + threadIdx.x;
    if (threadIdx.x < 128) as[threadIdx.x] = a_heads[hd * 128 + threadIdx.x];
    __syncthreads();
    const float4* hp = (const float4*)g_hcat + (size_t)i * (FIN / 4) + hd * (FH / 4);
    float s1 = 0.f, s2 = 0.f;
#pragma unroll
    for (int k = 0; k < 16; ++k) {
        float4 v = hp[k];
        s1 = fmaf(v.x, as[k * 4 + 0], s1);
        s1 = fmaf(v.y, as[k * 4 + 1], s1);
        s1 = fmaf(v.z, as[k * 4 + 2], s1);
        s1 = fmaf(v.w, as[k * 4 + 3], s1);
        s2 = fmaf(v.x, as[64 + k * 4 + 0], s2);
        s2 = fmaf(v.y, as[64 + k * 4 + 1], s2);
        s2 = fmaf(v.z, as[64 + k * 4 + 2], s2);
        s2 = fmaf(v.w, as[64 + k * 4 + 3], s2);
    }
    g_s1[hd * Nn + i] = s1 * LOG2E;
    g_s2[hd * Nn + i] = s2 * LOG2E;
}

// ---------------- K3: layer-1 attention via mma.sync tf32 ----------------
// 512 thr = 16 warps = 4 heads x 4 i-quarters. i-tile 128, j-split 3, BJ 32.
__global__ __launch_bounds__(512) void k3_mma() {
    __shared__ uint32_t Hs[Hh][64][36];
    const int tid = threadIdx.x;
    const int lane = tid & 31, wid = tid >> 5;
    const int h = wid >> 2, iq = wid & 3;
    const int tg = lane >> 2, tig = lane & 3;
    const int i0 = blockIdx.x * 128;
    const int js = blockIdx.y;
    const int jw0 = js * (KS3 / 32);

    float C[2][8][4] = {};
    float den[2][2] = {};
    float s1v[2][2];
#pragma unroll
    for (int mt = 0; mt < 2; ++mt) {
        int r = iq * 32 + mt * 16 + tg;
        s1v[mt][0] = g_s1[h * Nn + i0 + r];
        s1v[mt][1] = g_s1[h * Nn + i0 + r + 8];
    }

    for (int t = 0; t < KS3 / 32; ++t) {
        const int j0 = js * KS3 + t * 32;
        __syncthreads();
        // stage H^T tile (tf32-converted): 256 f-rows x 32 j
        {
            const int f = tid >> 1, q = tid & 1;
            const int hh = f >> 6, fl = f & 63;
#pragma unroll
            for (int k4 = 0; k4 < 4; ++k4) {
                float4 v = *(const float4*)&g_hT[(size_t)f * Nn + j0 + q * 16 + k4 * 4];
                uint4 u = make_uint4(f2tf32(v.x), f2tf32(v.y), f2tf32(v.z), f2tf32(v.w));
                *(uint4*)&Hs[hh][fl][q * 16 + k4 * 4] = u;
            }
        }
        __syncthreads();
        uint32_t mk[2][2];
#pragma unroll
        for (int mt = 0; mt < 2; ++mt)
#pragma unroll
            for (int rr = 0; rr < 2; ++rr) {
                int row = i0 + iq * 32 + mt * 16 + tg + rr * 8;
                mk[mt][rr] = g_adjbits[(size_t)row * NW + jw0 + t];
            }
        float s2v[4][2];
#pragma unroll
        for (int kc = 0; kc < 4; ++kc) {
            s2v[kc][0] = __ldg(&g_s2[h * Nn + j0 + kc * 8 + tig]);
            s2v[kc][1] = __ldg(&g_s2[h * Nn + j0 + kc * 8 + tig + 4]);
        }
#pragma unroll
        for (int kc = 0; kc < 4; ++kc) {
            uint32_t B[8][2];
#pragma unroll
            for (int nt = 0; nt < 8; ++nt) {
                B[nt][0] = Hs[h][nt * 8 + tg][kc * 8 + tig];
                B[nt][1] = Hs[h][nt * 8 + tg][kc * 8 + tig + 4];
            }
            const int c0 = kc * 8 + tig, c1 = c0 + 4;
            uint32_t A[2][4];
#pragma unroll
            for (int mt = 0; mt < 2; ++mt) {
                float e, w;
                e = s1v[mt][0] + s2v[kc][0]; e = fmaxf(e, 0.2f * e); w = ex2f(e);
                w = ((mk[mt][0] >> c0) & 1u) ? w : 0.f; den[mt][0] += w; A[mt][0] = f2tf32(w);
                e = s1v[mt][1] + s2v[kc][0]; e = fmaxf(e, 0.2f * e); w = ex2f(e);
                w = ((mk[mt][1] >> c0) & 1u) ? w : 0.f; den[mt][1] += w; A[mt][1] = f2tf32(w);
                e = s1v[mt][0] + s2v[kc][1]; e = fmaxf(e, 0.2f * e); w = ex2f(e);
                w = ((mk[mt][0] >> c1) & 1u) ? w : 0.f; den[mt][0] += w; A[mt][2] = f2tf32(w);
                e = s1v[mt][1] + s2v[kc][1]; e = fmaxf(e, 0.2f * e); w = ex2f(e);
                w = ((mk[mt][1] >> c1) & 1u) ? w : 0.f; den[mt][1] += w; A[mt][3] = f2tf32(w);
            }
#pragma unroll
            for (int mt = 0; mt < 2; ++mt)
#pragma unroll
                for (int nt = 0; nt < 8; ++nt)
                    mma_tf32(C[mt][nt], A[mt], B[nt]);
        }
    }
    // denominators
#pragma unroll
    for (int mt = 0; mt < 2; ++mt)
#pragma unroll
        for (int rr = 0; rr < 2; ++rr) {
            float v = den[mt][rr];
            v += __shfl_xor_sync(0xffffffffu, v, 1);
            v += __shfl_xor_sync(0xffffffffu, v, 2);
            if (tig == 0)
                g_pden[(js * Hh + h) * Nn + i0 + iq * 32 + mt * 16 + tg + rr * 8] = v;
        }
    // numerator writes
    float* pn = g_pnum + (size_t)js * Nn * FIN;
#pragma unroll
    for (int mt = 0; mt < 2; ++mt) {
        int r = i0 + iq * 32 + mt * 16 + tg;
#pragma unroll
        for (int nt = 0; nt < 8; ++nt) {
            int f = h * 64 + nt * 8 + tig * 2;
            *(float2*)&pn[(size_t)r * FIN + f]       = make_float2(C[mt][nt][0], C[mt][nt][1]);
            *(float2*)&pn[(size_t)(r + 8) * FIN + f] = make_float2(C[mt][nt][2], C[mt][nt][3]);
        }
    }
}

// ---------------- K3b: combine j-splits, normalize, elu, head-mean ----------------
__global__ __launch_bounds__(256) void k3b_combine() {
    const int idx = blockIdx.x * 256 + threadIdx.x;
    const int i = idx >> 6, f = idx & 63;
    float x2v = 0.f;
#pragma unroll
    for (int hd = 0; hd < Hh; ++hd) {
        float num = 0.f, dsum = 0.f;
#pragma unroll
        for (int js = 0; js < JSPLIT; ++js) {
            num  += g_pnum[(size_t)js * Nn * FIN + (size_t)i * FIN + hd * FH + f];
            dsum += g_pden[(js * Hh + hd) * Nn + i];
        }
        float o = num / dsum;
        o = (o > 0.f) ? o : (__expf(o) - 1.f);
        x2v += o;
    }
    g_x2[idx] = x2v * 0.25f;
}

// ---------------- K4: h2 = x2 @ W_out ----------------
__global__ __launch_bounds__(256) void k4_gemm2(const float* __restrict__ Wo) {
    __shared__ float Ws[64 * 32];
    __shared__ float xs[8][64];
    const int tid = threadIdx.x;
    const int i0 = blockIdx.x * 8;
    const int li = tid >> 5, f = tid & 31;
    for (int t = tid; t < 2048; t += 256) Ws[t] = Wo[t];
    for (int t = tid; t < 512; t += 256) xs[t >> 6][t & 63] = g_x2[(i0 + (t >> 6)) * 64 + (t & 63)];
    __syncthreads();
    float acc = 0.f;
#pragma unroll
    for (int k = 0; k < 64; ++k) acc = fmaf(xs[li][k], Ws[k * 32 + f], acc);
    g_h2[(i0 + li) * 32 + f] = acc;
}

// ---------------- K5: s1b/s2b (pre-scaled by log2e) ----------------
__global__ __launch_bounds__(256) void k5_scores2(const float* __restrict__ ao) {
    __shared__ float as[64];
    const int i = blockIdx.x * 256 + threadIdx.x;
    if (threadIdx.x < 64) as[threadIdx.x] = ao[threadIdx.x];
    __syncthreads();
    const float* hr = g_h2 + (size_t)i * 32;
    float s1 = 0.f, s2 = 0.f;
#pragma unroll
    for (int k = 0; k < 32; ++k) {
        float v = hr[k];
        s1 = fmaf(v, as[k], s1);
        s2 = fmaf(v, as[32 + k], s2);
    }
    g_s1b[i] = s1 * LOG2E;
    g_s2b[i] = s2 * LOG2E;
}

// ---------------- K6: layer-2 attention via mma.sync tf32 ----------------
// 256 thr = 8 warps = 4 i-quarters x 2 f-halves. i-tile 64, j-split 3, BJ 32.
#define KS6 (Nn / JSPLIT)   // 2048
__global__ __launch_bounds__(256) void k6_mma() {
    __shared__ uint32_t Hs2[32][40];
    const int tid = threadIdx.x;
    const int lane = tid & 31, wid = tid >> 5;
    const int iq = wid & 3, fh = wid >> 2;
    const int tg = lane >> 2, tig = lane & 3;
    const int i0 = blockIdx.x * 64;
    const int js = blockIdx.y;
    const int jw0 = js * (KS6 / 32);

    float C[2][4] = {};
    float den[2] = {};
    float s1v[2];
    s1v[0] = g_s1b[i0 + iq * 16 + tg];
    s1v[1] = g_s1b[i0 + iq * 16 + tg + 8];

    for (int t = 0; t < KS6 / 32; ++t) {
        const int j0 = js * KS6 + t * 32;
        __syncthreads();
        {
            const int row = tid >> 3, q = tid & 7;
            float4 v = *(const float4*)&g_h2[(size_t)(j0 + row) * FO + q * 4];
            uint4 u = make_uint4(f2tf32(v.x), f2tf32(v.y), f2tf32(v.z), f2tf32(v.w));
            *(uint4*)&Hs2[row][q * 4] = u;
        }
        __syncthreads();
        uint32_t mk[2];
        mk[0] = g_adjbits[(size_t)(i0 + iq * 16 + tg) * NW + jw0 + t];
        mk[1] = g_adjbits[(size_t)(i0 + iq * 16 + tg + 8) * NW + jw0 + t];
        float s2v[4][2];
#pragma unroll
        for (int kc = 0; kc < 4; ++kc) {
            s2v[kc][0] = __ldg(&g_s2b[j0 + kc * 8 + tig]);
            s2v[kc][1] = __ldg(&g_s2b[j0 + kc * 8 + tig + 4]);
        }
#pragma unroll
        for (int kc = 0; kc < 4; ++kc) {
            uint32_t B[2][2];
#pragma unroll
            for (int nt = 0; nt < 2; ++nt) {
                int f = fh * 16 + nt * 8 + tg;
                B[nt][0] = Hs2[kc * 8 + tig][f];
                B[nt][1] = Hs2[kc * 8 + tig + 4][f];
            }
            const int c0 = kc * 8 + tig, c1 = c0 + 4;
            uint32_t A[4];
            float e, w;
            e = s1v[0] + s2v[kc][0]; e = fmaxf(e, 0.2f * e); w = ex2f(e);
            w = ((mk[0] >> c0) & 1u) ? w : 0.f; den[0] += w; A[0] = f2tf32(w);
            e = s1v[1] + s2v[kc][0]; e = fmaxf(e, 0.2f * e); w = ex2f(e);
            w = ((mk[1] >> c0) & 1u) ? w : 0.f; den[1] += w; A[1] = f2tf32(w);
            e = s1v[0] + s2v[kc][1]; e = fmaxf(e, 0.2f * e); w = ex2f(e);
            w = ((mk[0] >> c1) & 1u) ? w : 0.f; den[0] += w; A[2] = f2tf32(w);
            e = s1v[1] + s2v[kc][1]; e = fmaxf(e, 0.2f * e); w = ex2f(e);
            w = ((mk[1] >> c1) & 1u) ? w : 0.f; den[1] += w; A[3] = f2tf32(w);
#pragma unroll
            for (int nt = 0; nt < 2; ++nt)
                mma_tf32(C[nt], A, B[nt]);
        }
    }
#pragma unroll
    for (int rr = 0; rr < 2; ++rr) {
        float v = den[rr];
        v += __shfl_xor_sync(0xffffffffu, v, 1);
        v += __shfl_xor_sync(0xffffffffu, v, 2);
        if (tig == 0 && fh == 0)
            g_p2den[js * Nn + i0 + iq * 16 + tg + rr * 8] = v;
    }
    float* pn = g_p2num + (size_t)js * Nn * FO;
    {
        int r = i0 + iq * 16 + tg;
#pragma unroll
        for (int nt = 0; nt < 2; ++nt) {
            int f = fh * 16 + nt * 8 + tig * 2;
            *(float2*)&pn[(size_t)r * FO + f]       = make_float2(C[nt][0], C[nt][1]);
            *(float2*)&pn[(size_t)(r + 8) * FO + f] = make_float2(C[nt][2], C[nt][3]);
        }
    }
}

// ---------------- K6b: combine, normalize, elu ----------------
__global__ __launch_bounds__(256) void k6b_combine(float* __restrict__ out) {
    const int idx = blockIdx.x * 256 + threadIdx.x;   // < Nn*FO
    const int i = idx >> 5;
    float num = 0.f, den = 0.f;
#pragma unroll
    for (int js = 0; js < JSPLIT; ++js) {
        num += g_p2num[(size_t)js * Nn * FO + idx];
        den += g_p2den[js * Nn + i];
    }
    float o = num / den;
    o = (o > 0.f) ? o : (__expf(o) - 1.f);
    out[idx] = o;
}

// ---------------- launch ----------------
extern "C" void kernel_launch(void* const* d_in, const int* in_sizes, int n_in,
                              void* d_out, int out_size) {
    (void)in_sizes; (void)n_in; (void)out_size;
    const float* x   = (const float*)d_in[0];
    const int*   adj = (const int*)d_in[1];
    const float* Wh  = (const float*)d_in[2];
    const float* ah  = (const float*)d_in[3];
    const float* Wo  = (const float*)d_in[4];
    const float* ao  = (const float*)d_in[5];
    float* out = (float*)d_out;

    kprep        <<<(Nn * NW) / 8, 256>>>(adj);
    k1_gemm      <<<dim3(Nn / 64, Hh), 256>>>(x, Wh);
    k1t_transpose<<<dim3(Nn / 32, FIN / 32), 256>>>();
    k2_scores    <<<dim3(Nn / 256, Hh), 256>>>(ah);
    k3_mma       <<<dim3(Nn / 128, JSPLIT), 512>>>();
    k3b_combine  <<<(Nn * FH) / 256, 256>>>();
    k4_gemm2     <<<Nn / 8, 256>>>(Wo);
    k5_scores2   <<<Nn / 256, 256>>>(ao);
    k6_mma       <<<dim3(Nn / 64, JSPLIT), 256>>>();
    k6b_combine  <<<(Nn * FO) / 256, 256>>>(out);
}

// round 15
// speedup vs baseline: 3.8934x; 1.0239x over previous
#include <cuda_runtime.h>
#include <cstdint>

#define Nn   6144
#define FIN  256
#define FH   64
#define Hh   4
#define FO   32
#define JSPLIT 3
#define KS3  (Nn / JSPLIT)       // 2048
#define NW   (Nn / 32)           // 192
#define LOG2E 1.4426950408889634f

// ---------------- scratch ----------------
__device__ __align__(16) float    g_WT[FIN * FIN];       // Wcat^T [n=256][k=256]
__device__ __align__(16) uint32_t g_hT32[FIN * Nn];      // h^T, tf32-prerounded fp32 bits
__device__ float    g_s1[Hh * Nn];
__device__ float    g_s2[Hh * Nn];
__device__ uint32_t g_adjbits[Nn * NW];
__device__ float    g_pnum[(size_t)JSPLIT * Nn * FIN];
__device__ float    g_pden[JSPLIT * Hh * Nn];
__device__ float    g_x2[Nn * FH];
__device__ float    g_h2[Nn * FO];
__device__ float    g_s1b[Nn];
__device__ float    g_s2b[Nn];
__device__ float    g_p2num[JSPLIT * Nn * FO];
__device__ float    g_p2den[JSPLIT * Nn];

// ---------------- helpers ----------------
__device__ __forceinline__ float ex2f(float x) {
    float y; asm("ex2.approx.f32 %0, %1;" : "=f"(y) : "f"(x)); return y;
}
__device__ __forceinline__ uint32_t f2tf32(float x) {
    uint32_t r; asm("cvt.rna.tf32.f32 %0, %1;" : "=r"(r) : "f"(x)); return r;
}
__device__ __forceinline__ void mma_tf32(float* c, const uint32_t* a, const uint32_t* b) {
    asm volatile(
        "mma.sync.aligned.m16n8k8.row.col.f32.tf32.tf32.f32 "
        "{%0,%1,%2,%3}, {%4,%5,%6,%7}, {%8,%9}, {%0,%1,%2,%3};\n"
        : "+f"(c[0]), "+f"(c[1]), "+f"(c[2]), "+f"(c[3])
        : "r"(a[0]), "r"(a[1]), "r"(a[2]), "r"(a[3]), "r"(b[0]), "r"(b[1]));
}
__device__ __forceinline__ uint32_t sptr(const void* p) {
    return (uint32_t)__cvta_generic_to_shared(p);
}
__device__ __forceinline__ void cp16(uint32_t dst, const void* src) {
    asm volatile("cp.async.ca.shared.global [%0], [%1], 16;" :: "r"(dst), "l"(src) : "memory");
}
#define CP_COMMIT() asm volatile("cp.async.commit_group;" ::: "memory")
#define CP_WAIT1()  asm volatile("cp.async.wait_group 1;" ::: "memory")

__device__ __forceinline__ float wc(float s1, float s2, uint32_t mask, int c) {
    float e = s1 + s2;
    e = fmaxf(e, 0.2f * e);
    float w = ex2f(e);
    return ((mask >> c) & 1u) ? w : 0.f;
}

// ---------------- Kprep: pack adjacency to bitmasks ----------------
__global__ __launch_bounds__(256) void kprep(const int* __restrict__ adj) {
    const int gw = (blockIdx.x * 256 + threadIdx.x) >> 5;
    const int lane = threadIdx.x & 31;
    int v = adj[(size_t)gw * 32 + lane];
    unsigned m = __ballot_sync(0xffffffffu, v > 0);
    if (lane == 0) g_adjbits[gw] = m;
}

// ---------------- KprepW: W_cat^T [n][k] ----------------
__global__ __launch_bounds__(256) void kprepW(const float* __restrict__ Wh) {
    int e = blockIdx.x * 256 + threadIdx.x;     // 65536
    int n = e >> 8, k = e & 255;
    g_WT[n * 256 + k] = Wh[(n >> 6) * (256 * 64) + k * 64 + (n & 63)];
}

// ---------------- K1: h = x @ Wcat via 3xTF32 mma (fp32-grade); fused transpose + scores ----------------
// grid 192 (32 rows/CTA), 256 thr = 8 warps (wy 2 x wx 4), warp tile 16x64, K-chunk 8.
__global__ __launch_bounds__(256) void k1_mma(const float* __restrict__ x,
                                              const float* __restrict__ ah) {
    __shared__ __align__(16) float xs[2][32][12];
    __shared__ __align__(16) float Ws[2][256][12];
    __shared__ __align__(16) float Cs[16][264];
    __shared__ float sa[512];
    const int tid = threadIdx.x, lane = tid & 31, wid = tid >> 5;
    const int wy = wid >> 2, wx = wid & 3, tg = lane >> 2, tig = lane & 3;
    const int i0 = blockIdx.x * 32;
    sa[tid] = ah[tid]; sa[tid + 256] = ah[tid + 256];

    float acc[8][4] = {};

    auto stage = [&](int it, int b) {
        const int kk = it * 8;
#pragma unroll
        for (int c = 0; c < 2; ++c) {
            int ch = tid + c * 256;
            int n = ch >> 1, hf = ch & 1;
            cp16(sptr(&Ws[b][n][hf * 4]), &g_WT[n * 256 + kk + hf * 4]);
        }
        if (tid < 64) {
            int r = tid >> 1, hf = tid & 1;
            cp16(sptr(&xs[b][r][hf * 4]), &x[(size_t)(i0 + r) * 256 + kk + hf * 4]);
        }
    };

    stage(0, 0); CP_COMMIT();
    stage(1, 1); CP_COMMIT();

    for (int it = 0; it < 32; ++it) {
        const int b = it & 1;
        CP_WAIT1();
        __syncthreads();
        // A fragments: hi/lo split for 3xTF32
        const int m0 = wy * 16 + tg;
        float av[4] = { xs[b][m0][tig], xs[b][m0 + 8][tig],
                        xs[b][m0][tig + 4], xs[b][m0 + 8][tig + 4] };
        uint32_t Ah[4], Al[4];
#pragma unroll
        for (int u = 0; u < 4; ++u) {
            Ah[u] = f2tf32(av[u]);
            Al[u] = f2tf32(av[u] - __uint_as_float(Ah[u]));
        }
#pragma unroll
        for (int nt = 0; nt < 8; ++nt) {
            const int n = wx * 64 + nt * 8 + tg;
            float b0 = Ws[b][n][tig], b1 = Ws[b][n][tig + 4];
            uint32_t Bh[2] = { f2tf32(b0), f2tf32(b1) };
            uint32_t Bl[2] = { f2tf32(b0 - __uint_as_float(Bh[0])),
                               f2tf32(b1 - __uint_as_float(Bh[1])) };
            mma_tf32(acc[nt], Ah, Bh);
            mma_tf32(acc[nt], Al, Bh);
            mma_tf32(acc[nt], Ah, Bl);
        }
        __syncthreads();
        // FIX: always commit one group per iteration so wait_group 1 always
        // drains the group feeding the NEXT iteration (incl. the last tiles).
        if (it + 2 < 32) stage(it + 2, b);
        CP_COMMIT();
    }

    // epilogue: two 16-row phases through Cs
#pragma unroll
    for (int ph = 0; ph < 2; ++ph) {
        __syncthreads();
        if (wy == ph) {
#pragma unroll
            for (int nt = 0; nt < 8; ++nt) {
                int col = wx * 64 + nt * 8 + tig * 2;
                Cs[tg][col]     = acc[nt][0];
                Cs[tg][col + 1] = acc[nt][1];
                Cs[tg + 8][col]     = acc[nt][2];
                Cs[tg + 8][col + 1] = acc[nt][3];
            }
        }
        __syncthreads();
        // write h^T as tf32-prerounded fp32 bits
#pragma unroll
        for (int c = 0; c < 16; ++c) {
            int idx = tid + c * 256;          // 0..4095
            int f = idx >> 4, r = idx & 15;
            g_hT32[(size_t)f * Nn + i0 + ph * 16 + r] = f2tf32(Cs[r][f]);
        }
        // scores (from fp32-grade h)
        if (tid < 64) {
            int r = tid & 15, hh = tid >> 4;
            float s1 = 0.f, s2 = 0.f;
#pragma unroll
            for (int f = 0; f < 64; ++f) {
                float v = Cs[r][hh * 64 + f];
                s1 = fmaf(v, sa[hh * 128 + f], s1);
                s2 = fmaf(v, sa[hh * 128 + 64 + f], s2);
            }
            int gi = i0 + ph * 16 + r;
            g_s1[hh * Nn + gi] = s1 * LOG2E;
            g_s2[hh * Nn + gi] = s2 * LOG2E;
        }
    }
}

// ---------------- K3: layer-1 attention via tf32 mma, cp.async double buffer ----------------
// grid (48, 3), 512 thr = 16 warps = 4 heads x 4 i-quarters; tile 128 rows x 32 j.
// H tile in SMEM: swizzled pitch-32: word(row, col) at row*32 + (col ^ ((row&7)*4)).
__global__ __launch_bounds__(512) void k3_mma() {
    extern __shared__ __align__(16) uint32_t Hdyn[];   // 2 x 8192 words = 64 KB
    const int tid = threadIdx.x, lane = tid & 31, wid = tid >> 5;
    const int h = wid >> 2, iq = wid & 3, tg = lane >> 2, tig = lane & 3;
    const int i0 = blockIdx.x * 128;
    const int js = blockIdx.y;
    const int jw0 = js * (KS3 / 32);
    const int NIT = KS3 / 32;   // 64

    int srow[4], sq[4]; uint32_t sdst[4];
#pragma unroll
    for (int c = 0; c < 4; ++c) {
        int ch = c * 512 + tid;
        srow[c] = ch & 255; sq[c] = ch >> 8;
        sdst[c] = srow[c] * 32 + ((sq[c] * 4) ^ ((srow[c] & 7) * 4));
    }
    int bcol[4];
#pragma unroll
    for (int kc = 0; kc < 4; ++kc)
        bcol[kc] = (kc * 8 + tig) ^ (tg * 4);

    float C[2][8][4] = {};
    float den[2][2] = {};
    float s1v[2][2];
#pragma unroll
    for (int mt = 0; mt < 2; ++mt) {
        int r = iq * 32 + mt * 16 + tg;
        s1v[mt][0] = g_s1[h * Nn + i0 + r];
        s1v[mt][1] = g_s1[h * Nn + i0 + r + 8];
    }

    auto stage = [&](int t, int b) {
        const int j0 = js * KS3 + t * 32;
#pragma unroll
        for (int c = 0; c < 4; ++c)
            cp16(sptr(&Hdyn[b * 8192 + sdst[c]]),
                 &g_hT32[(size_t)srow[c] * Nn + j0 + sq[c] * 4]);
    };
    auto ldmask = [&](int t, uint32_t mk[2][2]) {
#pragma unroll
        for (int mt = 0; mt < 2; ++mt)
#pragma unroll
            for (int rr = 0; rr < 2; ++rr)
                mk[mt][rr] = g_adjbits[(size_t)(i0 + iq * 32 + mt * 16 + tg + rr * 8) * NW + jw0 + t];
    };
    auto lds2 = [&](int t, float s2p[4][2]) {
        const int j0 = js * KS3 + t * 32;
#pragma unroll
        for (int kc = 0; kc < 4; ++kc) {
            s2p[kc][0] = __ldg(&g_s2[h * Nn + j0 + kc * 8 + tig]);
            s2p[kc][1] = __ldg(&g_s2[h * Nn + j0 + kc * 8 + tig + 4]);
        }
    };

    stage(0, 0); CP_COMMIT();
    stage(1, 1); CP_COMMIT();
    uint32_t mkc[2][2]; float s2c[4][2];
    ldmask(0, mkc); lds2(0, s2c);

    for (int t = 0; t < NIT; ++t) {
        const int b = t & 1;
        CP_WAIT1();
        __syncthreads();
        uint32_t mkn[2][2]; float s2n[4][2];
        if (t + 1 < NIT) { ldmask(t + 1, mkn); lds2(t + 1, s2n); }

        const uint32_t* Hb = Hdyn + b * 8192;
#pragma unroll
        for (int kc = 0; kc < 4; ++kc) {
            uint32_t Bf[8][2];
#pragma unroll
            for (int nt = 0; nt < 8; ++nt) {
                const int ro = (h * 64 + nt * 8 + tg) * 32;
                Bf[nt][0] = Hb[ro + bcol[kc]];
                Bf[nt][1] = Hb[ro + (bcol[kc] ^ 4)];
            }
            const int c0 = kc * 8 + tig, c1 = c0 + 4;
#pragma unroll
            for (int mt = 0; mt < 2; ++mt) {
                float w00 = wc(s1v[mt][0], s2c[kc][0], mkc[mt][0], c0);
                float w10 = wc(s1v[mt][1], s2c[kc][0], mkc[mt][1], c0);
                float w01 = wc(s1v[mt][0], s2c[kc][1], mkc[mt][0], c1);
                float w11 = wc(s1v[mt][1], s2c[kc][1], mkc[mt][1], c1);
                den[mt][0] += w00 + w01;
                den[mt][1] += w10 + w11;
                uint32_t A[4] = { f2tf32(w00), f2tf32(w10), f2tf32(w01), f2tf32(w11) };
#pragma unroll
                for (int nt = 0; nt < 8; ++nt)
                    mma_tf32(C[mt][nt], A, Bf[nt]);
            }
        }
        __syncthreads();
        // FIX: always commit one group per iteration (see k1_mma).
        if (t + 2 < NIT) stage(t + 2, b);
        CP_COMMIT();
        if (t + 1 < NIT) {
#pragma unroll
            for (int mt = 0; mt < 2; ++mt) { mkc[mt][0] = mkn[mt][0]; mkc[mt][1] = mkn[mt][1]; }
#pragma unroll
            for (int kc = 0; kc < 4; ++kc) { s2c[kc][0] = s2n[kc][0]; s2c[kc][1] = s2n[kc][1]; }
        }
    }

    // denominators
#pragma unroll
    for (int mt = 0; mt < 2; ++mt)
#pragma unroll
        for (int rr = 0; rr < 2; ++rr) {
            float v = den[mt][rr];
            v += __shfl_xor_sync(0xffffffffu, v, 1);
            v += __shfl_xor_sync(0xffffffffu, v, 2);
            if (tig == 0)
                g_pden[(js * Hh + h) * Nn + i0 + iq * 32 + mt * 16 + tg + rr * 8] = v;
        }
    // numerators
    float* pn = g_pnum + (size_t)js * Nn * FIN;
#pragma unroll
    for (int mt = 0; mt < 2; ++mt) {
        int r = i0 + iq * 32 + mt * 16 + tg;
#pragma unroll
        for (int nt = 0; nt < 8; ++nt) {
            int f = h * 64 + nt * 8 + tig * 2;
            *(float2*)&pn[(size_t)r * FIN + f]       = make_float2(C[mt][nt][0], C[mt][nt][1]);
            *(float2*)&pn[(size_t)(r + 8) * FIN + f] = make_float2(C[mt][nt][2], C[mt][nt][3]);
        }
    }
}

// ---------------- K3b: combine j-splits, normalize, elu, head-mean ----------------
__global__ __launch_bounds__(256) void k3b_combine() {
    const int idx = blockIdx.x * 256 + threadIdx.x;
    const int i = idx >> 6, f = idx & 63;
    float x2v = 0.f;
#pragma unroll
    for (int hd = 0; hd < Hh; ++hd) {
        float num = 0.f, dsum = 0.f;
#pragma unroll
        for (int js = 0; js < JSPLIT; ++js) {
            num  += g_pnum[(size_t)js * Nn * FIN + (size_t)i * FIN + hd * FH + f];
            dsum += g_pden[(js * Hh + hd) * Nn + i];
        }
        float o = num / dsum;
        o = (o > 0.f) ? o : (__expf(o) - 1.f);
        x2v += o;
    }
    g_x2[idx] = x2v * 0.25f;
}

// ---------------- K4: h2 = x2 @ W_out ----------------
__global__ __launch_bounds__(256) void k4_gemm2(const float* __restrict__ Wo) {
    __shared__ float Ws[64 * 32];
    __shared__ float xs[8][64];
    const int tid = threadIdx.x;
    const int i0 = blockIdx.x * 8;
    const int li = tid >> 5, f = tid & 31;
    for (int t = tid; t < 2048; t += 256) Ws[t] = Wo[t];
    for (int t = tid; t < 512; t += 256) xs[t >> 6][t & 63] = g_x2[(i0 + (t >> 6)) * 64 + (t & 63)];
    __syncthreads();
    float acc = 0.f;
#pragma unroll
    for (int k = 0; k < 64; ++k) acc = fmaf(xs[li][k], Ws[k * 32 + f], acc);
    g_h2[(i0 + li) * 32 + f] = acc;
}

// ---------------- K5: s1b/s2b ----------------
__global__ __launch_bounds__(256) void k5_scores2(const float* __restrict__ ao) {
    __shared__ float as[64];
    const int i = blockIdx.x * 256 + threadIdx.x;
    if (threadIdx.x < 64) as[threadIdx.x] = ao[threadIdx.x];
    __syncthreads();
    const float* hr = g_h2 + (size_t)i * 32;
    float s1 = 0.f, s2 = 0.f;
#pragma unroll
    for (int k = 0; k < 32; ++k) {
        float v = hr[k];
        s1 = fmaf(v, as[k], s1);
        s2 = fmaf(v, as[32 + k], s2);
    }
    g_s1b[i] = s1 * LOG2E;
    g_s2b[i] = s2 * LOG2E;
}

// ---------------- K6: layer-2 attention via mma.sync tf32 ----------------
#define KS6 (Nn / JSPLIT)
__global__ __launch_bounds__(256) void k6_mma() {
    __shared__ uint32_t Hs2[32][40];
    const int tid = threadIdx.x;
    const int lane = tid & 31, wid = tid >> 5;
    const int iq = wid & 3, fh = wid >> 2;
    const int tg = lane >> 2, tig = lane & 3;
    const int i0 = blockIdx.x * 64;
    const int js = blockIdx.y;
    const int jw0 = js * (KS6 / 32);

    float C[2][4] = {};
    float den[2] = {};
    float s1v[2];
    s1v[0] = g_s1b[i0 + iq * 16 + tg];
    s1v[1] = g_s1b[i0 + iq * 16 + tg + 8];

    for (int t = 0; t < KS6 / 32; ++t) {
        const int j0 = js * KS6 + t * 32;
        __syncthreads();
        {
            const int row = tid >> 3, q = tid & 7;
            float4 v = *(const float4*)&g_h2[(size_t)(j0 + row) * FO + q * 4];
            uint4 u = make_uint4(f2tf32(v.x), f2tf32(v.y), f2tf32(v.z), f2tf32(v.w));
            *(uint4*)&Hs2[row][q * 4] = u;
        }
        __syncthreads();
        uint32_t mk[2];
        mk[0] = g_adjbits[(size_t)(i0 + iq * 16 + tg) * NW + jw0 + t];
        mk[1] = g_adjbits[(size_t)(i0 + iq * 16 + tg + 8) * NW + jw0 + t];
        float s2v[4][2];
#pragma unroll
        for (int kc = 0; kc < 4; ++kc) {
            s2v[kc][0] = __ldg(&g_s2b[j0 + kc * 8 + tig]);
            s2v[kc][1] = __ldg(&g_s2b[j0 + kc * 8 + tig + 4]);
        }
#pragma unroll
        for (int kc = 0; kc < 4; ++kc) {
            uint32_t B[2][2];
#pragma unroll
            for (int nt = 0; nt < 2; ++nt) {
                int f = fh * 16 + nt * 8 + tg;
                B[nt][0] = Hs2[kc * 8 + tig][f];
                B[nt][1] = Hs2[kc * 8 + tig + 4][f];
            }
            const int c0 = kc * 8 + tig, c1 = c0 + 4;
            uint32_t A[4];
            float w00 = wc(s1v[0], s2v[kc][0], mk[0], c0);
            float w10 = wc(s1v[1], s2v[kc][0], mk[1], c0);
            float w01 = wc(s1v[0], s2v[kc][1], mk[0], c1);
            float w11 = wc(s1v[1], s2v[kc][1], mk[1], c1);
            den[0] += w00 + w01; den[1] += w10 + w11;
            A[0] = f2tf32(w00); A[1] = f2tf32(w10); A[2] = f2tf32(w01); A[3] = f2tf32(w11);
#pragma unroll
            for (int nt = 0; nt < 2; ++nt)
                mma_tf32(C[nt], A, B[nt]);
        }
    }
#pragma unroll
    for (int rr = 0; rr < 2; ++rr) {
        float v = den[rr];
        v += __shfl_xor_sync(0xffffffffu, v, 1);
        v += __shfl_xor_sync(0xffffffffu, v, 2);
        if (tig == 0 && fh == 0)
            g_p2den[js * Nn + i0 + iq * 16 + tg + rr * 8] = v;
    }
    float* pn = g_p2num + (size_t)js * Nn * FO;
    {
        int r = i0 + iq * 16 + tg;
#pragma unroll
        for (int nt = 0; nt < 2; ++nt) {
            int f = fh * 16 + nt * 8 + tig * 2;
            *(float2*)&pn[(size_t)r * FO + f]       = make_float2(C[nt][0], C[nt][1]);
            *(float2*)&pn[(size_t)(r + 8) * FO + f] = make_float2(C[nt][2], C[nt][3]);
        }
    }
}

// ---------------- K6b: combine, normalize, elu ----------------
__global__ __launch_bounds__(256) void k6b_combine(float* __restrict__ out) {
    const int idx = blockIdx.x * 256 + threadIdx.x;
    const int i = idx >> 5;
    float num = 0.f, den = 0.f;
#pragma unroll
    for (int js = 0; js < JSPLIT; ++js) {
        num += g_p2num[(size_t)js * Nn * FO + idx];
        den += g_p2den[js * Nn + i];
    }
    float o = num / den;
    o = (o > 0.f) ? o : (__expf(o) - 1.f);
    out[idx] = o;
}

// ---------------- launch ----------------
extern "C" void kernel_launch(void* const* d_in, const int* in_sizes, int n_in,
                              void* d_out, int out_size) {
    (void)in_sizes; (void)n_in; (void)out_size;
    const float* x   = (const float*)d_in[0];
    const int*   adj = (const int*)d_in[1];
    const float* Wh  = (const float*)d_in[2];
    const float* ah  = (const float*)d_in[3];
    const float* Wo  = (const float*)d_in[4];
    const float* ao  = (const float*)d_in[5];
    float* out = (float*)d_out;

    cudaFuncSetAttribute(k3_mma, cudaFuncAttributeMaxDynamicSharedMemorySize, 65536);

    kprep      <<<(Nn * NW) / 8, 256>>>(adj);
    kprepW     <<<256, 256>>>(Wh);
    k1_mma     <<<Nn / 32, 256>>>(x, ah);
    k3_mma     <<<dim3(Nn / 128, JSPLIT), 512, 65536>>>();
    k3b_combine<<<(Nn * FH) / 256, 256>>>();
    k4_gemm2   <<<Nn / 8, 256>>>(Wo);
    k5_scores2 <<<Nn / 256, 256>>>(ao);
    k6_mma     <<<dim3(Nn / 64, JSPLIT), 256>>>();
    k6b_combine<<<(Nn * FO) / 256, 256>>>(out);
}